// round 16
// baseline (speedup 1.0000x reference)
#include <cuda_runtime.h>
#include <cuda_fp16.h>

#define B_ 4
#define N_ 2048
#define C_ 768
#define H_ 12
#define R_ 32
#define M_ (B_ * N_)          // 8192 rows
#define HR_ (H_ * R_)         // 384

#define QSCALE (0.125f * 1.44269504f)   // head_dim^-0.5 * log2(e)

// Scratch (device globals; no allocations allowed)
__device__ __half   g_xh[M_ * C_];
__device__ __half   g_wqt[HR_ * C_];
__device__ __half   g_wkt[HR_ * C_];
__device__ __half   g_wvt[HR_ * C_];
__device__ __half   g_wpt[C_ * HR_];
__device__ __half   g_qh[B_ * H_ * N_ * R_];
__device__ __half   g_kh[B_ * H_ * N_ * R_];
__device__ __half   g_vt[B_ * H_ * R_ * N_];   // v half, TRANSPOSED [B,H,R,N]
__device__ __half   g_oh[B_ * N_ * HR_];

// ---------------------------------------------------------------------------
// helpers
// ---------------------------------------------------------------------------
__device__ __forceinline__ float ex2(float x) {
    float r; asm("ex2.approx.ftz.f32 %0, %1;" : "=f"(r) : "f"(x)); return r;
}
__device__ __forceinline__ unsigned packh2(float lo, float hi) {
    __half2 h = __floats2half2_rn(lo, hi);
    return *(unsigned*)&h;
}
__device__ __forceinline__ void mma_f16(float* c, unsigned a0, unsigned a1,
                                        unsigned a2, unsigned a3,
                                        unsigned b0, unsigned b1) {
    asm("mma.sync.aligned.m16n8k16.row.col.f32.f16.f16.f32 "
        "{%0,%1,%2,%3},{%4,%5,%6,%7},{%8,%9},{%0,%1,%2,%3};"
        : "+f"(c[0]), "+f"(c[1]), "+f"(c[2]), "+f"(c[3])
        : "r"(a0), "r"(a1), "r"(a2), "r"(a3), "r"(b0), "r"(b1));
}
__device__ __forceinline__ void cpa16(unsigned dst, const void* src) {
    asm volatile("cp.async.cg.shared.global [%0], [%1], 16;" :: "r"(dst), "l"(src));
}
#define CP_COMMIT() asm volatile("cp.async.commit_group;" ::: "memory")
#define CP_WAIT1()  asm volatile("cp.async.wait_group 1;" ::: "memory")
#define CP_WAIT0()  asm volatile("cp.async.wait_group 0;" ::: "memory")

// ---------------------------------------------------------------------------
// Prep: x -> half
// ---------------------------------------------------------------------------
__global__ __launch_bounds__(256) void x_to_half_kernel(
    const float* __restrict__ x, __half* __restrict__ xh)
{
    int i = (blockIdx.x * 256 + threadIdx.x) * 8;
    float4 f0 = *(const float4*)(x + i);
    float4 f1 = *(const float4*)(x + i + 4);
    __half2 h0 = __floats2half2_rn(f0.x, f0.y);
    __half2 h1 = __floats2half2_rn(f0.z, f0.w);
    __half2 h2 = __floats2half2_rn(f1.x, f1.y);
    __half2 h3 = __floats2half2_rn(f1.z, f1.w);
    uint4 u = { *(unsigned*)&h0, *(unsigned*)&h1, *(unsigned*)&h2, *(unsigned*)&h3 };
    *(uint4*)(xh + i) = u;
}

// ---------------------------------------------------------------------------
// Prep: transpose W [K][N] float -> Wt [N][K] half. grid.z selects matrix.
// ---------------------------------------------------------------------------
__global__ __launch_bounds__(256) void w_transpose_kernel(
    const float* __restrict__ Wq, const float* __restrict__ Wk,
    const float* __restrict__ Wv, const float* __restrict__ Wp,
    __half* __restrict__ wqt, __half* __restrict__ wkt,
    __half* __restrict__ wvt, __half* __restrict__ wpt)
{
    __shared__ float t[32][33];
    const int z = blockIdx.z;
    const float* W = (z == 0) ? Wq : (z == 1) ? Wk : (z == 2) ? Wv : Wp;
    __half* Wt     = (z == 0) ? wqt : (z == 1) ? wkt : (z == 2) ? wvt : wpt;
    const int Kd = (z < 3) ? C_ : HR_;
    const int Nd = (z < 3) ? HR_ : C_;

    const int bx = blockIdx.x, by = blockIdx.y;
    if (bx * 32 >= Nd || by * 32 >= Kd) return;
    const int tx = threadIdx.x & 31;
    const int ty = threadIdx.x >> 5;   // 0..7

#pragma unroll
    for (int i = 0; i < 4; i++)
        t[ty + i * 8][tx] = W[(size_t)(by * 32 + ty + i * 8) * Nd + bx * 32 + tx];
    __syncthreads();
#pragma unroll
    for (int i = 0; i < 4; i++)
        Wt[(size_t)(bx * 32 + ty + i * 8) * Kd + by * 32 + tx] =
            __float2half_rn(t[tx][ty + i * 8]);
}

// ---------------------------------------------------------------------------
// FP16 tensor-core GEMM (unchanged from R10/R15 winner).
// ---------------------------------------------------------------------------
#define GS_STRIDE 20

template <int OUT>
__device__ __forceinline__ void gemm_f16_body(
    const __half* __restrict__ A, const __half* __restrict__ Wt,
    void* __restrict__ Cv, int K, int Nc, int rowBase, int colBase,
    float oscale)
{
    __shared__ unsigned As[128][GS_STRIDE];   // [m][word]
    __shared__ unsigned Ws[128][GS_STRIDE];   // [n][word]

    const int tid  = threadIdx.x;
    const int w    = tid >> 5;
    const int lane = tid & 31;
    const int g    = lane >> 2;
    const int tg   = lane & 3;
    const int m0   = (w >> 2) * 64;
    const int n0   = (w & 3) * 32;

    float acc[4][4][4] = {};
    uint4 pa[2], pw[2];

#pragma unroll
    for (int j = 0; j < 2; j++) {
        int idx = tid + j * 256;
        int row = idx >> 2, c4 = idx & 3;
        pa[j] = *(const uint4*)(A  + (size_t)(rowBase + row) * K + c4 * 8);
        pw[j] = *(const uint4*)(Wt + (size_t)(colBase + row) * K + c4 * 8);
    }
#pragma unroll
    for (int j = 0; j < 2; j++) {
        int idx = tid + j * 256;
        int row = idx >> 2, c4 = idx & 3;
        *(uint4*)&As[row][c4 * 4] = pa[j];
        *(uint4*)&Ws[row][c4 * 4] = pw[j];
    }
    __syncthreads();

    const int KT = K >> 5;
    for (int kt = 0; kt < KT; kt++) {
        if (kt + 1 < KT) {
            int kq = (kt + 1) * 32;
#pragma unroll
            for (int j = 0; j < 2; j++) {
                int idx = tid + j * 256;
                int row = idx >> 2, c4 = idx & 3;
                pa[j] = *(const uint4*)(A  + (size_t)(rowBase + row) * K + kq + c4 * 8);
                pw[j] = *(const uint4*)(Wt + (size_t)(colBase + row) * K + kq + c4 * 8);
            }
        }

#pragma unroll
        for (int c = 0; c < 2; c++) {
            unsigned b0[4], b1[4];
#pragma unroll
            for (int ni = 0; ni < 4; ni++) {
                int n = n0 + ni * 8 + g;
                b0[ni] = Ws[n][c * 8 + tg];
                b1[ni] = Ws[n][c * 8 + tg + 4];
            }
#pragma unroll
            for (int mi = 0; mi < 4; mi++) {
                int mr = m0 + mi * 16 + g;
                unsigned a0 = As[mr][c * 8 + tg];
                unsigned a1 = As[mr + 8][c * 8 + tg];
                unsigned a2 = As[mr][c * 8 + tg + 4];
                unsigned a3 = As[mr + 8][c * 8 + tg + 4];
#pragma unroll
                for (int ni = 0; ni < 4; ni++)
                    mma_f16(acc[mi][ni], a0, a1, a2, a3, b0[ni], b1[ni]);
            }
        }

        if (kt + 1 < KT) {
            __syncthreads();
#pragma unroll
            for (int j = 0; j < 2; j++) {
                int idx = tid + j * 256;
                int row = idx >> 2, c4 = idx & 3;
                *(uint4*)&As[row][c4 * 4] = pa[j];
                *(uint4*)&Ws[row][c4 * 4] = pw[j];
            }
            __syncthreads();
        }
    }

#pragma unroll
    for (int mi = 0; mi < 4; mi++) {
        int row0 = rowBase + m0 + mi * 16 + g;
        int row1 = row0 + 8;
#pragma unroll
        for (int ni = 0; ni < 4; ni++) {
            int col = colBase + n0 + ni * 8 + 2 * tg;
            if (OUT == 0) {
                float* Cout = (float*)Cv;
                float2 f0 = { acc[mi][ni][0], acc[mi][ni][1] };
                float2 f1 = { acc[mi][ni][2], acc[mi][ni][3] };
                *(float2*)&Cout[(size_t)row0 * Nc + col] = f0;
                *(float2*)&Cout[(size_t)row1 * Nc + col] = f1;
            } else if (OUT == 1) {
                __half* Ch = (__half*)Cv;
                int h = col >> 5, rr = col & (R_ - 1);
                int b0r = row0 >> 11, n0r = row0 & (N_ - 1);
                int b1r = row1 >> 11, n1r = row1 & (N_ - 1);
                size_t i0 = ((((size_t)b0r * H_ + h) * N_) + n0r) * R_ + rr;
                size_t i1 = ((((size_t)b1r * H_ + h) * N_) + n1r) * R_ + rr;
                *(unsigned*)(Ch + i0) = packh2(acc[mi][ni][0] * oscale, acc[mi][ni][1] * oscale);
                *(unsigned*)(Ch + i1) = packh2(acc[mi][ni][2] * oscale, acc[mi][ni][3] * oscale);
            } else {  // OUT == 3: V transposed [B,H,R,N]
                __half* Ct = (__half*)Cv;
                int h = col >> 5, rr = col & (R_ - 1);
                int b0r = row0 >> 11, n0r = row0 & (N_ - 1);
                int b1r = row1 >> 11, n1r = row1 & (N_ - 1);
                Ct[(((size_t)b0r * H_ + h) * R_ + rr)     * N_ + n0r] = __float2half_rn(acc[mi][ni][0]);
                Ct[(((size_t)b0r * H_ + h) * R_ + rr + 1) * N_ + n0r] = __float2half_rn(acc[mi][ni][1]);
                Ct[(((size_t)b1r * H_ + h) * R_ + rr)     * N_ + n1r] = __float2half_rn(acc[mi][ni][2]);
                Ct[(((size_t)b1r * H_ + h) * R_ + rr + 1) * N_ + n1r] = __float2half_rn(acc[mi][ni][3]);
            }
        }
    }
}

__global__ __launch_bounds__(256) void qkv_proj_kernel(
    const __half* __restrict__ xh,
    const __half* __restrict__ wqt, const __half* __restrict__ wkt,
    const __half* __restrict__ wvt,
    __half* __restrict__ oq, __half* __restrict__ ok,
    __half* __restrict__ ovt)
{
    const int z = blockIdx.z;
    const int rb = blockIdx.y * 128, cb = blockIdx.x * 128;
    if (z == 0)      gemm_f16_body<1>(xh, wqt, oq, C_, HR_, rb, cb, QSCALE);
    else if (z == 1) gemm_f16_body<1>(xh, wkt, ok, C_, HR_, rb, cb, 1.0f);
    else             gemm_f16_body<3>(xh, wvt, ovt, C_, HR_, rb, cb, 1.0f);
}

__global__ __launch_bounds__(256) void out_proj_kernel(
    const __half* __restrict__ A, const __half* __restrict__ wpt,
    float* __restrict__ Cout)
{
    gemm_f16_body<0>(A, wpt, Cout, HR_, C_, blockIdx.y * 128, blockIdx.x * 128, 1.0f);
}

// ---------------------------------------------------------------------------
// Flash attention: R15 structure (4 warps x 32 q-rows, 3 CTAs/SM) with K/V
// staging moved to cp.async.cg double-buffering. Copy of tile t+1 runs in the
// async path fully overlapped with compute on tile t; no prefetch registers.
// ---------------------------------------------------------------------------
#define KS_STRIDE 20
#define VT_STRIDE 36
#define PS_STRIDE 36
#define KS_WORDS (64 * KS_STRIDE)
#define VT_WORDS (32 * VT_STRIDE)
#define SMEM_ATTN ((2 * (KS_WORDS + VT_WORDS) + 128 * PS_STRIDE) * 4)

__global__ __launch_bounds__(128, 3) void attn_tc_kernel(
    const __half* __restrict__ q, const __half* __restrict__ k,
    const __half* __restrict__ vt, __half* __restrict__ o)
{
    extern __shared__ unsigned smem[];
    unsigned (*KsBuf[2])[KS_STRIDE];
    unsigned (*VtBuf[2])[VT_STRIDE];
    KsBuf[0] = (unsigned(*)[KS_STRIDE])smem;
    VtBuf[0] = (unsigned(*)[VT_STRIDE])(smem + KS_WORDS);
    KsBuf[1] = (unsigned(*)[KS_STRIDE])(smem + KS_WORDS + VT_WORDS);
    VtBuf[1] = (unsigned(*)[VT_STRIDE])(smem + 2 * KS_WORDS + VT_WORDS);
    unsigned (*Ps)[PS_STRIDE] = (unsigned(*)[PS_STRIDE])(smem + 2 * (KS_WORDS + VT_WORDS));

    const int tid  = threadIdx.x;
    const int w    = tid >> 5;
    const int lane = tid & 31;
    const int g    = lane >> 2;
    const int tg   = lane & 3;
    const int bh   = blockIdx.y;
    const int qbase = blockIdx.x * 128;

    // Q fragments (half, pre-scaled)
    unsigned qa[2][2][4];
#pragma unroll
    for (int mi = 0; mi < 2; mi++) {
        const __half* q0 = q + ((size_t)bh * N_ + qbase + w * 32 + mi * 16 + g) * R_;
        const __half* q1 = q0 + 8 * R_;
#pragma unroll
        for (int c = 0; c < 2; c++) {
            qa[mi][c][0] = *(const unsigned*)(q0 + c * 16 + 2 * tg);
            qa[mi][c][1] = *(const unsigned*)(q1 + c * 16 + 2 * tg);
            qa[mi][c][2] = *(const unsigned*)(q0 + c * 16 + 2 * tg + 8);
            qa[mi][c][3] = *(const unsigned*)(q1 + c * 16 + 2 * tg + 8);
        }
    }

    float m[2][2] = { {-1e30f, -1e30f}, {-1e30f, -1e30f} };
    float l[2][2] = {};
    float oacc[2][4][4] = {};

    const uint4* kg = (const uint4*)(k  + (size_t)bh * N_ * R_);   // tile: 256 uint4
    const uint4* vg = (const uint4*)(vt + (size_t)bh * R_ * N_);   // row r: 256 uint4

    // per-thread staging targets (2 uint4 each for K and V)
    const int ki0 = tid,        kkey0 = ki0 >> 2, kc0 = ki0 & 3;
    const int ki1 = tid + 128,  kkey1 = ki1 >> 2, kc1 = ki1 & 3;
    const int vi0 = tid,        vr0 = vi0 >> 3,  vc0 = vi0 & 7;
    const int vi1 = tid + 128,  vr1 = vi1 >> 3,  vc1 = vi1 & 7;

    // issue async copy of tile kt into buffer buf
    auto issue_tile = [&](int buf, int kt) {
        const uint4* kb = kg + kt * 256;
        cpa16((unsigned)__cvta_generic_to_shared(&KsBuf[buf][kkey0][kc0 * 4]), kb + ki0);
        cpa16((unsigned)__cvta_generic_to_shared(&KsBuf[buf][kkey1][kc1 * 4]), kb + ki1);
        cpa16((unsigned)__cvta_generic_to_shared(&VtBuf[buf][vr0][vc0 * 4]), vg + vr0 * 256 + kt * 8 + vc0);
        cpa16((unsigned)__cvta_generic_to_shared(&VtBuf[buf][vr1][vc1 * 4]), vg + vr1 * 256 + kt * 8 + vc1);
        CP_COMMIT();
    };

    // prologue: fill both buffers
    issue_tile(0, 0);
    issue_tile(1, 1);
    CP_WAIT1();          // tile 0 resident
    __syncthreads();

    const int NT = N_ / 64;   // 32 tiles
    int p = 0;
    for (int kt = 0; kt < NT; kt++) {
        unsigned (*Ks)[KS_STRIDE]  = KsBuf[p];
        unsigned (*Vts)[VT_STRIDE] = VtBuf[p];

        // ---- S = Q @ K^T (fp16 k16) ----
        float s[2][8][4];
#pragma unroll
        for (int mi = 0; mi < 2; mi++)
#pragma unroll
            for (int nt = 0; nt < 8; nt++) {
                s[mi][nt][0] = 0; s[mi][nt][1] = 0; s[mi][nt][2] = 0; s[mi][nt][3] = 0;
            }
#pragma unroll
        for (int nt = 0; nt < 8; nt++) {
#pragma unroll
            for (int c = 0; c < 2; c++) {
                unsigned b0 = Ks[nt * 8 + g][c * 8 + tg];
                unsigned b1 = Ks[nt * 8 + g][c * 8 + tg + 4];
                mma_f16(s[0][nt], qa[0][c][0], qa[0][c][1], qa[0][c][2], qa[0][c][3], b0, b1);
                mma_f16(s[1][nt], qa[1][c][0], qa[1][c][1], qa[1][c][2], qa[1][c][3], b0, b1);
            }
        }

        // ---- online softmax + P store (half2) ----
#pragma unroll
        for (int mi = 0; mi < 2; mi++) {
            float r0 = -1e30f, r1 = -1e30f;
#pragma unroll
            for (int nt = 0; nt < 8; nt++) {
                r0 = fmaxf(r0, fmaxf(s[mi][nt][0], s[mi][nt][1]));
                r1 = fmaxf(r1, fmaxf(s[mi][nt][2], s[mi][nt][3]));
            }
            r0 = fmaxf(r0, __shfl_xor_sync(0xffffffff, r0, 1));
            r0 = fmaxf(r0, __shfl_xor_sync(0xffffffff, r0, 2));
            r1 = fmaxf(r1, __shfl_xor_sync(0xffffffff, r1, 1));
            r1 = fmaxf(r1, __shfl_xor_sync(0xffffffff, r1, 2));

            float mn0 = fmaxf(m[mi][0], r0), mn1 = fmaxf(m[mi][1], r1);
            float al0 = ex2(m[mi][0] - mn0), al1 = ex2(m[mi][1] - mn1);
            m[mi][0] = mn0; m[mi][1] = mn1;
            l[mi][0] *= al0; l[mi][1] *= al1;
#pragma unroll
            for (int nt = 0; nt < 4; nt++) {
                oacc[mi][nt][0] *= al0; oacc[mi][nt][1] *= al0;
                oacc[mi][nt][2] *= al1; oacc[mi][nt][3] *= al1;
            }

            const int prow0 = w * 32 + mi * 16 + g;
#pragma unroll
            for (int nt = 0; nt < 8; nt++) {
                float p0 = ex2(s[mi][nt][0] - mn0);
                float p1 = ex2(s[mi][nt][1] - mn0);
                float p2 = ex2(s[mi][nt][2] - mn1);
                float p3 = ex2(s[mi][nt][3] - mn1);
                l[mi][0] += p0 + p1;
                l[mi][1] += p2 + p3;
                Ps[prow0][nt * 4 + tg]     = packh2(p0, p1);
                Ps[prow0 + 8][nt * 4 + tg] = packh2(p2, p3);
            }
        }
        __syncwarp();

        // ---- O += P @ V (fp16 k16), B-frags shared across both m-tiles ----
#pragma unroll
        for (int ks = 0; ks < 4; ks++) {
            unsigned b0[4], b1[4];
#pragma unroll
            for (int nt = 0; nt < 4; nt++) {
                int n = nt * 8 + g;
                b0[nt] = Vts[n][ks * 8 + tg];
                b1[nt] = Vts[n][ks * 8 + tg + 4];
            }
#pragma unroll
            for (int mi = 0; mi < 2; mi++) {
                const int prow = w * 32 + mi * 16 + g;
                unsigned a0 = Ps[prow][ks * 8 + tg];
                unsigned a1 = Ps[prow + 8][ks * 8 + tg];
                unsigned a2 = Ps[prow][ks * 8 + tg + 4];
                unsigned a3 = Ps[prow + 8][ks * 8 + tg + 4];
#pragma unroll
                for (int nt = 0; nt < 4; nt++)
                    mma_f16(oacc[mi][nt], a0, a1, a2, a3, b0[nt], b1[nt]);
            }
        }

        // ---- rotate buffers ----
        if (kt + 1 < NT) {
            __syncthreads();                 // all threads done reading buf p
            if (kt + 2 < NT) {
                issue_tile(p, kt + 2);       // refill just-freed buffer
                CP_WAIT1();                  // tile kt+1 (older group) resident
            } else {
                CP_WAIT0();                  // only tile kt+1 pending
            }
            __syncthreads();
            p ^= 1;
        }
    }

    // ---- finalize: normalize, store half ----
    const int b = bh / H_;
    const int h = bh % H_;
#pragma unroll
    for (int mi = 0; mi < 2; mi++) {
        float l0 = l[mi][0], l1 = l[mi][1];
        l0 += __shfl_xor_sync(0xffffffff, l0, 1);
        l0 += __shfl_xor_sync(0xffffffff, l0, 2);
        l1 += __shfl_xor_sync(0xffffffff, l1, 1);
        l1 += __shfl_xor_sync(0xffffffff, l1, 2);
        const float inv0 = 1.0f / l0;
        const float inv1 = 1.0f / l1;

        const int row0 = qbase + w * 32 + mi * 16 + g;
        const int row1 = row0 + 8;
        __half* o0 = o + (((size_t)b * N_ + row0) * H_ + h) * R_;
        __half* o1 = o + (((size_t)b * N_ + row1) * H_ + h) * R_;
#pragma unroll
        for (int nt = 0; nt < 4; nt++) {
            int col = nt * 8 + 2 * tg;
            *(unsigned*)(o0 + col) = packh2(oacc[mi][nt][0] * inv0, oacc[mi][nt][1] * inv0);
            *(unsigned*)(o1 + col) = packh2(oacc[mi][nt][2] * inv1, oacc[mi][nt][3] * inv1);
        }
    }
}

// ---------------------------------------------------------------------------
extern "C" void kernel_launch(void* const* d_in, const int* in_sizes, int n_in,
                              void* d_out, int out_size)
{
    const float* x  = (const float*)d_in[0];
    const float* Wq = (const float*)d_in[1];
    const float* Wk = (const float*)d_in[2];
    const float* Wv = (const float*)d_in[3];
    const float* Wp = (const float*)d_in[4];
    float* out = (float*)d_out;

    __half *xh, *wqt, *wkt, *wvt, *wpt, *qh, *kh, *vth, *oh;
    cudaGetSymbolAddress((void**)&xh,  g_xh);
    cudaGetSymbolAddress((void**)&wqt, g_wqt);
    cudaGetSymbolAddress((void**)&wkt, g_wkt);
    cudaGetSymbolAddress((void**)&wvt, g_wvt);
    cudaGetSymbolAddress((void**)&wpt, g_wpt);
    cudaGetSymbolAddress((void**)&qh,  g_qh);
    cudaGetSymbolAddress((void**)&kh,  g_kh);
    cudaGetSymbolAddress((void**)&vth, g_vt);
    cudaGetSymbolAddress((void**)&oh,  g_oh);

    static bool attr_set = false;
    if (!attr_set) {
        cudaFuncSetAttribute(attn_tc_kernel,
                             cudaFuncAttributeMaxDynamicSharedMemorySize, SMEM_ATTN);
        attr_set = true;
    }

    // prep: x->half, W transposes->half
    x_to_half_kernel<<<M_ * C_ / 2048, 256>>>(x, xh);
    dim3 gT(C_ / 32, C_ / 32, 4);
    w_transpose_kernel<<<gT, 256>>>(Wq, Wk, Wv, Wp, wqt, wkt, wvt, wpt);

    // QKV projections (fp16 tensor core; V written transposed)
    dim3 gProj(HR_ / 128, M_ / 128, 3);
    qkv_proj_kernel<<<gProj, 256>>>(xh, wqt, wkt, wvt, qh, kh, vth);

    // attention (cp.async double-buffered, 3 CTAs/SM)
    dim3 gAttn(N_ / 128, B_ * H_);
    attn_tc_kernel<<<gAttn, 128, SMEM_ATTN>>>(qh, kh, vth, oh);

    // output projection
    dim3 gOut(C_ / 128, M_ / 128);
    out_proj_kernel<<<gOut, 256>>>(oh, wpt, out);
}

// round 17
// speedup vs baseline: 1.0852x; 1.0852x over previous
#include <cuda_runtime.h>
#include <cuda_fp16.h>

#define B_ 4
#define N_ 2048
#define C_ 768
#define H_ 12
#define R_ 32
#define M_ (B_ * N_)          // 8192 rows
#define HR_ (H_ * R_)         // 384

#define QSCALE (0.125f * 1.44269504f)   // head_dim^-0.5 * log2(e)

// Scratch (device globals; no allocations allowed)
__device__ __half   g_wqt[HR_ * C_];
__device__ __half   g_wkt[HR_ * C_];
__device__ __half   g_wvt[HR_ * C_];
__device__ __half   g_wpt[C_ * HR_];
__device__ __half   g_qh[B_ * H_ * N_ * R_];
__device__ __half   g_kh[B_ * H_ * N_ * R_];
__device__ __half   g_vt[B_ * H_ * R_ * N_];   // v half, TRANSPOSED [B,H,R,N]
__device__ __half   g_oh[B_ * N_ * HR_];

// ---------------------------------------------------------------------------
// helpers
// ---------------------------------------------------------------------------
__device__ __forceinline__ float ex2(float x) {
    float r; asm("ex2.approx.ftz.f32 %0, %1;" : "=f"(r) : "f"(x)); return r;
}
__device__ __forceinline__ unsigned packh2(float lo, float hi) {
    __half2 h = __floats2half2_rn(lo, hi);
    return *(unsigned*)&h;
}
__device__ __forceinline__ void mma_f16(float* c, unsigned a0, unsigned a1,
                                        unsigned a2, unsigned a3,
                                        unsigned b0, unsigned b1) {
    asm("mma.sync.aligned.m16n8k16.row.col.f32.f16.f16.f32 "
        "{%0,%1,%2,%3},{%4,%5,%6,%7},{%8,%9},{%0,%1,%2,%3};"
        : "+f"(c[0]), "+f"(c[1]), "+f"(c[2]), "+f"(c[3])
        : "r"(a0), "r"(a1), "r"(a2), "r"(a3), "r"(b0), "r"(b1));
}

// ---------------------------------------------------------------------------
// Prep: transpose W [K][N] float -> Wt [N][K] half. grid.z selects matrix.
// ---------------------------------------------------------------------------
__global__ __launch_bounds__(256) void w_transpose_kernel(
    const float* __restrict__ Wq, const float* __restrict__ Wk,
    const float* __restrict__ Wv, const float* __restrict__ Wp,
    __half* __restrict__ wqt, __half* __restrict__ wkt,
    __half* __restrict__ wvt, __half* __restrict__ wpt)
{
    __shared__ float t[32][33];
    const int z = blockIdx.z;
    const float* W = (z == 0) ? Wq : (z == 1) ? Wk : (z == 2) ? Wv : Wp;
    __half* Wt     = (z == 0) ? wqt : (z == 1) ? wkt : (z == 2) ? wvt : wpt;
    const int Kd = (z < 3) ? C_ : HR_;
    const int Nd = (z < 3) ? HR_ : C_;

    const int bx = blockIdx.x, by = blockIdx.y;
    if (bx * 32 >= Nd || by * 32 >= Kd) return;
    const int tx = threadIdx.x & 31;
    const int ty = threadIdx.x >> 5;   // 0..7

#pragma unroll
    for (int i = 0; i < 4; i++)
        t[ty + i * 8][tx] = W[(size_t)(by * 32 + ty + i * 8) * Nd + bx * 32 + tx];
    __syncthreads();
#pragma unroll
    for (int i = 0; i < 4; i++)
        Wt[(size_t)(bx * 32 + ty + i * 8) * Kd + by * 32 + tx] =
            __float2half_rn(t[tx][ty + i * 8]);
}

// ---------------------------------------------------------------------------
// FP16 tensor-core GEMM. BM=128, BN=128, BK=32, 256 thr, 8 warps (2x4),
// warp tile 64x32 (4x4 m16n8 frags), m16n8k16.
// AFP32 = 1: A operand is FLOAT in gmem; converted to half in the staging
// path (fuses the former x_to_half pass into the GEMM).
// OUT 0: float C row-major. OUT 1: half scatter [B,H,N,R] (scale folded).
// OUT 3: half scatter TRANSPOSED [B,H,R,N] (for V).
// ---------------------------------------------------------------------------
#define GS_STRIDE 20

template <int OUT, int AFP32>
__device__ __forceinline__ void gemm_f16_body(
    const void* __restrict__ Av, const __half* __restrict__ Wt,
    void* __restrict__ Cv, int K, int Nc, int rowBase, int colBase,
    float oscale)
{
    __shared__ unsigned As[128][GS_STRIDE];   // [m][word]
    __shared__ unsigned Ws[128][GS_STRIDE];   // [n][word]

    const __half* Ah = (const __half*)Av;
    const float*  Af = (const float*)Av;

    const int tid  = threadIdx.x;
    const int w    = tid >> 5;
    const int lane = tid & 31;
    const int g    = lane >> 2;
    const int tg   = lane & 3;
    const int m0   = (w >> 2) * 64;
    const int n0   = (w & 3) * 32;

    float acc[4][4][4] = {};
    uint4  pah[2];          // half path
    float4 paf[2][2];       // float path (two float4 per uint4)
    uint4  pw[2];

#pragma unroll
    for (int j = 0; j < 2; j++) {
        int idx = tid + j * 256;
        int row = idx >> 2, c4 = idx & 3;
        if (AFP32) {
            paf[j][0] = *(const float4*)(Af + (size_t)(rowBase + row) * K + c4 * 8);
            paf[j][1] = *(const float4*)(Af + (size_t)(rowBase + row) * K + c4 * 8 + 4);
        } else {
            pah[j] = *(const uint4*)(Ah + (size_t)(rowBase + row) * K + c4 * 8);
        }
        pw[j] = *(const uint4*)(Wt + (size_t)(colBase + row) * K + c4 * 8);
    }
#pragma unroll
    for (int j = 0; j < 2; j++) {
        int idx = tid + j * 256;
        int row = idx >> 2, c4 = idx & 3;
        uint4 u;
        if (AFP32) {
            u.x = packh2(paf[j][0].x, paf[j][0].y);
            u.y = packh2(paf[j][0].z, paf[j][0].w);
            u.z = packh2(paf[j][1].x, paf[j][1].y);
            u.w = packh2(paf[j][1].z, paf[j][1].w);
        } else u = pah[j];
        *(uint4*)&As[row][c4 * 4] = u;
        *(uint4*)&Ws[row][c4 * 4] = pw[j];
    }
    __syncthreads();

    const int KT = K >> 5;
    for (int kt = 0; kt < KT; kt++) {
        if (kt + 1 < KT) {
            int kq = (kt + 1) * 32;
#pragma unroll
            for (int j = 0; j < 2; j++) {
                int idx = tid + j * 256;
                int row = idx >> 2, c4 = idx & 3;
                if (AFP32) {
                    paf[j][0] = *(const float4*)(Af + (size_t)(rowBase + row) * K + kq + c4 * 8);
                    paf[j][1] = *(const float4*)(Af + (size_t)(rowBase + row) * K + kq + c4 * 8 + 4);
                } else {
                    pah[j] = *(const uint4*)(Ah + (size_t)(rowBase + row) * K + kq + c4 * 8);
                }
                pw[j] = *(const uint4*)(Wt + (size_t)(colBase + row) * K + kq + c4 * 8);
            }
        }

#pragma unroll
        for (int c = 0; c < 2; c++) {
            unsigned b0[4], b1[4];
#pragma unroll
            for (int ni = 0; ni < 4; ni++) {
                int n = n0 + ni * 8 + g;
                b0[ni] = Ws[n][c * 8 + tg];
                b1[ni] = Ws[n][c * 8 + tg + 4];
            }
#pragma unroll
            for (int mi = 0; mi < 4; mi++) {
                int mr = m0 + mi * 16 + g;
                unsigned a0 = As[mr][c * 8 + tg];
                unsigned a1 = As[mr + 8][c * 8 + tg];
                unsigned a2 = As[mr][c * 8 + tg + 4];
                unsigned a3 = As[mr + 8][c * 8 + tg + 4];
#pragma unroll
                for (int ni = 0; ni < 4; ni++)
                    mma_f16(acc[mi][ni], a0, a1, a2, a3, b0[ni], b1[ni]);
            }
        }

        if (kt + 1 < KT) {
            __syncthreads();
#pragma unroll
            for (int j = 0; j < 2; j++) {
                int idx = tid + j * 256;
                int row = idx >> 2, c4 = idx & 3;
                uint4 u;
                if (AFP32) {
                    u.x = packh2(paf[j][0].x, paf[j][0].y);
                    u.y = packh2(paf[j][0].z, paf[j][0].w);
                    u.z = packh2(paf[j][1].x, paf[j][1].y);
                    u.w = packh2(paf[j][1].z, paf[j][1].w);
                } else u = pah[j];
                *(uint4*)&As[row][c4 * 4] = u;
                *(uint4*)&Ws[row][c4 * 4] = pw[j];
            }
            __syncthreads();
        }
    }

#pragma unroll
    for (int mi = 0; mi < 4; mi++) {
        int row0 = rowBase + m0 + mi * 16 + g;
        int row1 = row0 + 8;
#pragma unroll
        for (int ni = 0; ni < 4; ni++) {
            int col = colBase + n0 + ni * 8 + 2 * tg;
            if (OUT == 0) {
                float* Cout = (float*)Cv;
                float2 f0 = { acc[mi][ni][0], acc[mi][ni][1] };
                float2 f1 = { acc[mi][ni][2], acc[mi][ni][3] };
                *(float2*)&Cout[(size_t)row0 * Nc + col] = f0;
                *(float2*)&Cout[(size_t)row1 * Nc + col] = f1;
            } else if (OUT == 1) {
                __half* Ch = (__half*)Cv;
                int h = col >> 5, rr = col & (R_ - 1);
                int b0r = row0 >> 11, n0r = row0 & (N_ - 1);
                int b1r = row1 >> 11, n1r = row1 & (N_ - 1);
                size_t i0 = ((((size_t)b0r * H_ + h) * N_) + n0r) * R_ + rr;
                size_t i1 = ((((size_t)b1r * H_ + h) * N_) + n1r) * R_ + rr;
                *(unsigned*)(Ch + i0) = packh2(acc[mi][ni][0] * oscale, acc[mi][ni][1] * oscale);
                *(unsigned*)(Ch + i1) = packh2(acc[mi][ni][2] * oscale, acc[mi][ni][3] * oscale);
            } else {  // OUT == 3: V transposed [B,H,R,N]
                __half* Ct = (__half*)Cv;
                int h = col >> 5, rr = col & (R_ - 1);
                int b0r = row0 >> 11, n0r = row0 & (N_ - 1);
                int b1r = row1 >> 11, n1r = row1 & (N_ - 1);
                Ct[(((size_t)b0r * H_ + h) * R_ + rr)     * N_ + n0r] = __float2half_rn(acc[mi][ni][0]);
                Ct[(((size_t)b0r * H_ + h) * R_ + rr + 1) * N_ + n0r] = __float2half_rn(acc[mi][ni][1]);
                Ct[(((size_t)b1r * H_ + h) * R_ + rr)     * N_ + n1r] = __float2half_rn(acc[mi][ni][2]);
                Ct[(((size_t)b1r * H_ + h) * R_ + rr + 1) * N_ + n1r] = __float2half_rn(acc[mi][ni][3]);
            }
        }
    }
}

__global__ __launch_bounds__(256) void qkv_proj_kernel(
    const float* __restrict__ x,
    const __half* __restrict__ wqt, const __half* __restrict__ wkt,
    const __half* __restrict__ wvt,
    __half* __restrict__ oq, __half* __restrict__ ok,
    __half* __restrict__ ovt)
{
    const int z = blockIdx.z;
    const int rb = blockIdx.y * 128, cb = blockIdx.x * 128;
    if (z == 0)      gemm_f16_body<1, 1>(x, wqt, oq, C_, HR_, rb, cb, QSCALE);
    else if (z == 1) gemm_f16_body<1, 1>(x, wkt, ok, C_, HR_, rb, cb, 1.0f);
    else             gemm_f16_body<3, 1>(x, wvt, ovt, C_, HR_, rb, cb, 1.0f);
}

__global__ __launch_bounds__(256) void out_proj_kernel(
    const __half* __restrict__ A, const __half* __restrict__ wpt,
    float* __restrict__ Cout)
{
    gemm_f16_body<0, 0>(A, wpt, Cout, HR_, C_, blockIdx.y * 128, blockIdx.x * 128, 1.0f);
}

// ---------------------------------------------------------------------------
// Flash attention: EXACT R15 winner (4 warps x 32 q-rows, single K/V buffer,
// LDG at loop top, STS at loop bottom, fused softmax, shared B-frags,
// __launch_bounds__(128, 3) for 3 CTAs/SM). FROZEN — all scheduling variants
// (R11/R12/R13/R16) regressed.
// ---------------------------------------------------------------------------
#define KS_STRIDE 20
#define VT_STRIDE 36
#define PS_STRIDE 36
#define SMEM_ATTN ((64 * KS_STRIDE + 32 * VT_STRIDE + 128 * PS_STRIDE) * 4)

__global__ __launch_bounds__(128, 3) void attn_tc_kernel(
    const __half* __restrict__ q, const __half* __restrict__ k,
    const __half* __restrict__ vt, __half* __restrict__ o)
{
    extern __shared__ unsigned smem[];
    unsigned (*Ks)[KS_STRIDE]  = (unsigned(*)[KS_STRIDE])smem;
    unsigned (*Vts)[VT_STRIDE] = (unsigned(*)[VT_STRIDE])(smem + 64 * KS_STRIDE);
    unsigned (*Ps)[PS_STRIDE]  = (unsigned(*)[PS_STRIDE])(smem + 64 * KS_STRIDE + 32 * VT_STRIDE);

    const int tid  = threadIdx.x;
    const int w    = tid >> 5;
    const int lane = tid & 31;
    const int g    = lane >> 2;
    const int tg   = lane & 3;
    const int bh   = blockIdx.y;
    const int qbase = blockIdx.x * 128;

    // Q fragments (half, pre-scaled)
    unsigned qa[2][2][4];
#pragma unroll
    for (int mi = 0; mi < 2; mi++) {
        const __half* q0 = q + ((size_t)bh * N_ + qbase + w * 32 + mi * 16 + g) * R_;
        const __half* q1 = q0 + 8 * R_;
#pragma unroll
        for (int c = 0; c < 2; c++) {
            qa[mi][c][0] = *(const unsigned*)(q0 + c * 16 + 2 * tg);
            qa[mi][c][1] = *(const unsigned*)(q1 + c * 16 + 2 * tg);
            qa[mi][c][2] = *(const unsigned*)(q0 + c * 16 + 2 * tg + 8);
            qa[mi][c][3] = *(const unsigned*)(q1 + c * 16 + 2 * tg + 8);
        }
    }

    float m[2][2] = { {-1e30f, -1e30f}, {-1e30f, -1e30f} };
    float l[2][2] = {};
    float oacc[2][4][4] = {};

    const uint4* kg = (const uint4*)(k  + (size_t)bh * N_ * R_);   // 8 halves each
    const uint4* vg = (const uint4*)(vt + (size_t)bh * R_ * N_);   // row r: 256 uint4

    // preload tile 0
#pragma unroll
    for (int j = 0; j < 2; j++) {           // K: 256 uint4/tile
        int idx = tid + j * 128;
        int key = idx >> 2, c4 = idx & 3;
        *(uint4*)&Ks[key][c4 * 4] = kg[idx];
    }
#pragma unroll
    for (int j = 0; j < 2; j++) {           // Vt: 32 rows x 8 uint4
        int idx = tid + j * 128;
        int r = idx >> 3, c = idx & 7;
        *(uint4*)&Vts[r][c * 4] = vg[r * 256 + c];
    }
    __syncthreads();

    const int NT = N_ / 64;
    for (int kt = 0; kt < NT; kt++) {
        uint4 kr[2], vr[2];
        if (kt + 1 < NT) {
            int kbase = (kt + 1) * 256;
#pragma unroll
            for (int j = 0; j < 2; j++) kr[j] = kg[kbase + tid + j * 128];
#pragma unroll
            for (int j = 0; j < 2; j++) {
                int idx = tid + j * 128;
                int r = idx >> 3, c = idx & 7;
                vr[j] = vg[r * 256 + (kt + 1) * 8 + c];
            }
        }

        // ---- S = Q @ K^T (fp16 k16) ----
        float s[2][8][4];
#pragma unroll
        for (int mi = 0; mi < 2; mi++)
#pragma unroll
            for (int nt = 0; nt < 8; nt++) {
                s[mi][nt][0] = 0; s[mi][nt][1] = 0; s[mi][nt][2] = 0; s[mi][nt][3] = 0;
            }
#pragma unroll
        for (int nt = 0; nt < 8; nt++) {
#pragma unroll
            for (int c = 0; c < 2; c++) {
                unsigned b0 = Ks[nt * 8 + g][c * 8 + tg];
                unsigned b1 = Ks[nt * 8 + g][c * 8 + tg + 4];
                mma_f16(s[0][nt], qa[0][c][0], qa[0][c][1], qa[0][c][2], qa[0][c][3], b0, b1);
                mma_f16(s[1][nt], qa[1][c][0], qa[1][c][1], qa[1][c][2], qa[1][c][3], b0, b1);
            }
        }

        // ---- online softmax + P store (half2) ----
#pragma unroll
        for (int mi = 0; mi < 2; mi++) {
            float r0 = -1e30f, r1 = -1e30f;
#pragma unroll
            for (int nt = 0; nt < 8; nt++) {
                r0 = fmaxf(r0, fmaxf(s[mi][nt][0], s[mi][nt][1]));
                r1 = fmaxf(r1, fmaxf(s[mi][nt][2], s[mi][nt][3]));
            }
            r0 = fmaxf(r0, __shfl_xor_sync(0xffffffff, r0, 1));
            r0 = fmaxf(r0, __shfl_xor_sync(0xffffffff, r0, 2));
            r1 = fmaxf(r1, __shfl_xor_sync(0xffffffff, r1, 1));
            r1 = fmaxf(r1, __shfl_xor_sync(0xffffffff, r1, 2));

            float mn0 = fmaxf(m[mi][0], r0), mn1 = fmaxf(m[mi][1], r1);
            float al0 = ex2(m[mi][0] - mn0), al1 = ex2(m[mi][1] - mn1);
            m[mi][0] = mn0; m[mi][1] = mn1;
            l[mi][0] *= al0; l[mi][1] *= al1;
#pragma unroll
            for (int nt = 0; nt < 4; nt++) {
                oacc[mi][nt][0] *= al0; oacc[mi][nt][1] *= al0;
                oacc[mi][nt][2] *= al1; oacc[mi][nt][3] *= al1;
            }

            const int prow0 = w * 32 + mi * 16 + g;
#pragma unroll
            for (int nt = 0; nt < 8; nt++) {
                float p0 = ex2(s[mi][nt][0] - mn0);
                float p1 = ex2(s[mi][nt][1] - mn0);
                float p2 = ex2(s[mi][nt][2] - mn1);
                float p3 = ex2(s[mi][nt][3] - mn1);
                l[mi][0] += p0 + p1;
                l[mi][1] += p2 + p3;
                Ps[prow0][nt * 4 + tg]     = packh2(p0, p1);
                Ps[prow0 + 8][nt * 4 + tg] = packh2(p2, p3);
            }
        }
        __syncwarp();

        // ---- O += P @ V (fp16 k16), B-frags shared across both m-tiles ----
#pragma unroll
        for (int ks = 0; ks < 4; ks++) {
            unsigned b0[4], b1[4];
#pragma unroll
            for (int nt = 0; nt < 4; nt++) {
                int n = nt * 8 + g;
                b0[nt] = Vts[n][ks * 8 + tg];
                b1[nt] = Vts[n][ks * 8 + tg + 4];
            }
#pragma unroll
            for (int mi = 0; mi < 2; mi++) {
                const int prow = w * 32 + mi * 16 + g;
                unsigned a0 = Ps[prow][ks * 8 + tg];
                unsigned a1 = Ps[prow + 8][ks * 8 + tg];
                unsigned a2 = Ps[prow][ks * 8 + tg + 4];
                unsigned a3 = Ps[prow + 8][ks * 8 + tg + 4];
#pragma unroll
                for (int nt = 0; nt < 4; nt++)
                    mma_f16(oacc[mi][nt], a0, a1, a2, a3, b0[nt], b1[nt]);
            }
        }

        if (kt + 1 < NT) {
            __syncthreads();
#pragma unroll
            for (int j = 0; j < 2; j++) {
                int idx = tid + j * 128;
                int key = idx >> 2, c4 = idx & 3;
                *(uint4*)&Ks[key][c4 * 4] = kr[j];
            }
#pragma unroll
            for (int j = 0; j < 2; j++) {
                int idx = tid + j * 128;
                int r = idx >> 3, c = idx & 7;
                *(uint4*)&Vts[r][c * 4] = vr[j];
            }
            __syncthreads();
        }
    }

    // ---- finalize: normalize, store half ----
    const int b = bh / H_;
    const int h = bh % H_;
#pragma unroll
    for (int mi = 0; mi < 2; mi++) {
        float l0 = l[mi][0], l1 = l[mi][1];
        l0 += __shfl_xor_sync(0xffffffff, l0, 1);
        l0 += __shfl_xor_sync(0xffffffff, l0, 2);
        l1 += __shfl_xor_sync(0xffffffff, l1, 1);
        l1 += __shfl_xor_sync(0xffffffff, l1, 2);
        const float inv0 = 1.0f / l0;
        const float inv1 = 1.0f / l1;

        const int row0 = qbase + w * 32 + mi * 16 + g;
        const int row1 = row0 + 8;
        __half* o0 = o + (((size_t)b * N_ + row0) * H_ + h) * R_;
        __half* o1 = o + (((size_t)b * N_ + row1) * H_ + h) * R_;
#pragma unroll
        for (int nt = 0; nt < 4; nt++) {
            int col = nt * 8 + 2 * tg;
            *(unsigned*)(o0 + col) = packh2(oacc[mi][nt][0] * inv0, oacc[mi][nt][1] * inv0);
            *(unsigned*)(o1 + col) = packh2(oacc[mi][nt][2] * inv1, oacc[mi][nt][3] * inv1);
        }
    }
}

// ---------------------------------------------------------------------------
extern "C" void kernel_launch(void* const* d_in, const int* in_sizes, int n_in,
                              void* d_out, int out_size)
{
    const float* x  = (const float*)d_in[0];
    const float* Wq = (const float*)d_in[1];
    const float* Wk = (const float*)d_in[2];
    const float* Wv = (const float*)d_in[3];
    const float* Wp = (const float*)d_in[4];
    float* out = (float*)d_out;

    __half *wqt, *wkt, *wvt, *wpt, *qh, *kh, *vth, *oh;
    cudaGetSymbolAddress((void**)&wqt, g_wqt);
    cudaGetSymbolAddress((void**)&wkt, g_wkt);
    cudaGetSymbolAddress((void**)&wvt, g_wvt);
    cudaGetSymbolAddress((void**)&wpt, g_wpt);
    cudaGetSymbolAddress((void**)&qh,  g_qh);
    cudaGetSymbolAddress((void**)&kh,  g_kh);
    cudaGetSymbolAddress((void**)&vth, g_vt);
    cudaGetSymbolAddress((void**)&oh,  g_oh);

    static bool attr_set = false;
    if (!attr_set) {
        cudaFuncSetAttribute(attn_tc_kernel,
                             cudaFuncAttributeMaxDynamicSharedMemorySize, SMEM_ATTN);
        attr_set = true;
    }

    // prep: W transposes -> half (x conversion fused into qkv staging)
    dim3 gT(C_ / 32, C_ / 32, 4);
    w_transpose_kernel<<<gT, 256>>>(Wq, Wk, Wv, Wp, wqt, wkt, wvt, wpt);

    // QKV projections (fp16 tensor core; float x converted in staging;
    // V written transposed)
    dim3 gProj(HR_ / 128, M_ / 128, 3);
    qkv_proj_kernel<<<gProj, 256>>>(x, wqt, wkt, wvt, qh, kh, vth);

    // attention (R15 exact, frozen)
    dim3 gAttn(N_ / 128, B_ * H_);
    attn_tc_kernel<<<gAttn, 128, SMEM_ATTN>>>(qh, kh, vth, oh);

    // output projection
    dim3 gOut(C_ / 128, M_ / 128);
    out_proj_kernel<<<gOut, 256>>>(oh, wpt, out);
}